// round 2
// baseline (speedup 1.0000x reference)
#include <cuda_runtime.h>

// Trilinear resample of (B=4, D=64, H=64, W=64, C=32) fp32, identity theta.
// Grid identity: f = 62*i/63  =>  i0 = max(i-1,0), t = 1 - i/63 (t=0 at i=0).
// Strip kernel: each thread walks 32 outputs along w for fixed (b,d,h,c4),
// computing the (y,z)-bilinear g(x) per x-column once and lerping along x:
//   out(w) = (1-tx)*g(w-1) + tx*g(w)
// => 4 float4 loads per output instead of 8 (halves L1 load wavefronts).

#define B_ 4
#define D_ 64
#define H_ 64
#define W_ 64
#define C4_ 8          // 32 channels / 4
#define STRIP_ 32
#define NSTRIP_ (W_ / STRIP_)

__global__ __launch_bounds__(256) void trilerp_strip_kernel(
    const float4* __restrict__ in, float4* __restrict__ out)
{
    const int tid = blockIdx.x * blockDim.x + threadIdx.x;
    // bits: c4[0:3) h[3:9) s[9:10) d[10:16) b[16:18)
    const int c4 = tid & (C4_ - 1);
    const int h  = (tid >> 3) & (H_ - 1);
    const int s  = (tid >> 9) & (NSTRIP_ - 1);
    const int d  = (tid >> 10) & (D_ - 1);
    const int b  = tid >> 16;

    // y/z corner + fractional weights (same math as reference, simplified)
    const float fy = (float)h * (62.0f / 63.0f);
    const float fz = (float)d * (62.0f / 63.0f);
    const int y0 = max(h - 1, 0);
    const int z0 = max(d - 1, 0);
    const float ty = fy - (float)y0;
    const float tz = fz - (float)z0;
    const float sy = 1.0f - ty;
    const float sz = 1.0f - tz;
    const float w00 = sy * sz;   // (y0, z0)
    const float w10 = ty * sz;   // (y1, z0)
    const float w01 = sy * tz;   // (y0, z1)
    const float w11 = ty * tz;   // (y1, z1)

    // row pointers (float4 units); element at column x is p + x*C4_
    const long rowY = (long)W_ * C4_;
    const long rowZ = (long)H_ * W_ * C4_;
    const float4* p00 = in + ((((long)b * D_ + z0) * H_ + y0) * W_) * C4_ + c4;
    const float4* p10 = p00 + rowY;
    const float4* p01 = p00 + rowZ;
    const float4* p11 = p01 + rowY;

    // bilinear (y,z) blend at x-column
    auto bilerp = [&](int x) -> float4 {
        const long o = (long)x * C4_;
        const float4 a = __ldg(p00 + o);
        const float4 bb = __ldg(p10 + o);
        const float4 c = __ldg(p01 + o);
        const float4 dd = __ldg(p11 + o);
        float4 g;
        g.x = fmaf(w11, dd.x, fmaf(w01, c.x, fmaf(w10, bb.x, w00 * a.x)));
        g.y = fmaf(w11, dd.y, fmaf(w01, c.y, fmaf(w10, bb.y, w00 * a.y)));
        g.z = fmaf(w11, dd.z, fmaf(w01, c.z, fmaf(w10, bb.z, w00 * a.z)));
        g.w = fmaf(w11, dd.w, fmaf(w01, c.w, fmaf(w10, bb.w, w00 * a.w)));
        return g;
    };

    const int ws = s * STRIP_;
    float4 gA = bilerp(max(ws - 1, 0));

    float4* po = out + ((((long)b * D_ + d) * H_ + h) * W_ + ws) * C4_ + c4;

    #pragma unroll 4
    for (int i = 0; i < STRIP_; ++i) {
        const int w = ws + i;
        const float4 gB = bilerp(w);
        // tx = fx - x0 = 1 - w/63 for w>=1; tx = 0 at w=0
        const float tx = (w == 0) ? 0.0f : (1.0f - (float)w * (1.0f / 63.0f));
        const float sx = 1.0f - tx;
        float4 r;
        r.x = fmaf(tx, gB.x, sx * gA.x);
        r.y = fmaf(tx, gB.y, sx * gA.y);
        r.z = fmaf(tx, gB.z, sx * gA.z);
        r.w = fmaf(tx, gB.w, sx * gA.w);
        po[(long)i * C4_] = r;
        gA = gB;
    }
}

extern "C" void kernel_launch(void* const* d_in, const int* in_sizes, int n_in,
                              void* d_out, int out_size)
{
    const float4* in = (const float4*)d_in[0];
    float4* out = (float4*)d_out;
    const int total_threads = B_ * D_ * H_ * C4_ * NSTRIP_;  // 262144
    const int threads = 256;
    const int blocks = total_threads / threads;               // 1024
    trilerp_strip_kernel<<<blocks, threads>>>(in, out);
}

// round 3
// speedup vs baseline: 1.1829x; 1.1829x over previous
#include <cuda_runtime.h>

// Trilinear resample of (B=4, D=64, H=64, W=64, C=32) fp32, identity theta.
// Grid identity: f = 62*i/63 => i0 = max(i-1,0); t = 1 - i/63 (t=0 at i=0).
// Each thread computes 2 adjacent w outputs (one float4 / 4 channels each):
//   needs x-columns {w-1, w, w+1}; bilerp each column in (y,z) once,
//   then two x-lerps. 12 independent loads per thread = 6 loads/output
//   (vs 8 naive), fully straight-line => high MLP, no serial chain.

#define B_ 4
#define D_ 64
#define H_ 64
#define W_ 64
#define C4_ 8          // 32 channels / 4

__global__ __launch_bounds__(256) void trilerp2_kernel(
    const float4* __restrict__ in, float4* __restrict__ out)
{
    const int tid = blockIdx.x * blockDim.x + threadIdx.x;
    // bits: c4[0:3) wp[3:8) h[8:14) d[14:20) b[20:22)
    const int c4 = tid & (C4_ - 1);
    const int wp = (tid >> 3) & 31;       // w-pair index: w = 2*wp, 2*wp+1
    const int h  = (tid >> 8) & (H_ - 1);
    const int d  = (tid >> 14) & (D_ - 1);
    const int b  = tid >> 20;

    const int w0i = 2 * wp;
    const int w1i = w0i + 1;

    // (y,z) corner + bilinear weights
    const float fy = (float)h * (62.0f / 63.0f);
    const float fz = (float)d * (62.0f / 63.0f);
    const int y0 = max(h - 1, 0);
    const int z0 = max(d - 1, 0);
    const float ty = fy - (float)y0;
    const float tz = fz - (float)z0;
    const float sy = 1.0f - ty;
    const float sz = 1.0f - tz;
    const float q00 = sy * sz;
    const float q10 = ty * sz;
    const float q01 = sy * tz;
    const float q11 = ty * tz;

    const long rowY = (long)W_ * C4_;
    const long rowZ = (long)H_ * W_ * C4_;
    const float4* p00 = in + ((((long)b * D_ + z0) * H_ + y0) * W_) * C4_ + c4;
    const float4* p10 = p00 + rowY;
    const float4* p01 = p00 + rowZ;
    const float4* p11 = p01 + rowY;

    const int xm = max(w0i - 1, 0);   // column for g(w-1); unused weight when w=0
    const long om = (long)xm  * C4_;
    const long o0 = (long)w0i * C4_;
    const long o1 = (long)w1i * C4_;

    // 12 independent loads
    const float4 am = __ldg(p00 + om), bm = __ldg(p10 + om),
                 cm = __ldg(p01 + om), dm = __ldg(p11 + om);
    const float4 a0 = __ldg(p00 + o0), b0 = __ldg(p10 + o0),
                 c0 = __ldg(p01 + o0), d0 = __ldg(p11 + o0);
    const float4 a1 = __ldg(p00 + o1), b1 = __ldg(p10 + o1),
                 c1 = __ldg(p01 + o1), d1 = __ldg(p11 + o1);

    // bilerp each column
    float4 gm, g0, g1;
    gm.x = fmaf(q11, dm.x, fmaf(q01, cm.x, fmaf(q10, bm.x, q00 * am.x)));
    gm.y = fmaf(q11, dm.y, fmaf(q01, cm.y, fmaf(q10, bm.y, q00 * am.y)));
    gm.z = fmaf(q11, dm.z, fmaf(q01, cm.z, fmaf(q10, bm.z, q00 * am.z)));
    gm.w = fmaf(q11, dm.w, fmaf(q01, cm.w, fmaf(q10, bm.w, q00 * am.w)));
    g0.x = fmaf(q11, d0.x, fmaf(q01, c0.x, fmaf(q10, b0.x, q00 * a0.x)));
    g0.y = fmaf(q11, d0.y, fmaf(q01, c0.y, fmaf(q10, b0.y, q00 * a0.y)));
    g0.z = fmaf(q11, d0.z, fmaf(q01, c0.z, fmaf(q10, b0.z, q00 * a0.z)));
    g0.w = fmaf(q11, d0.w, fmaf(q01, c0.w, fmaf(q10, b0.w, q00 * a0.w)));
    g1.x = fmaf(q11, d1.x, fmaf(q01, c1.x, fmaf(q10, b1.x, q00 * a1.x)));
    g1.y = fmaf(q11, d1.y, fmaf(q01, c1.y, fmaf(q10, b1.y, q00 * a1.y)));
    g1.z = fmaf(q11, d1.z, fmaf(q01, c1.z, fmaf(q10, b1.z, q00 * a1.z)));
    g1.w = fmaf(q11, d1.w, fmaf(q01, c1.w, fmaf(q10, b1.w, q00 * a1.w)));

    // x-lerps: out(w) = (1-tx)*g(w-1) + tx*g(w); tx = 1 - w/63 (w>=1), 0 at w=0
    const float tx0 = (w0i == 0) ? 0.0f : (1.0f - (float)w0i * (1.0f / 63.0f));
    const float tx1 = 1.0f - (float)w1i * (1.0f / 63.0f);   // w1i >= 1 always
    const float sx0 = 1.0f - tx0;
    const float sx1 = 1.0f - tx1;

    float4 r0, r1;
    r0.x = fmaf(tx0, g0.x, sx0 * gm.x);
    r0.y = fmaf(tx0, g0.y, sx0 * gm.y);
    r0.z = fmaf(tx0, g0.z, sx0 * gm.z);
    r0.w = fmaf(tx0, g0.w, sx0 * gm.w);
    r1.x = fmaf(tx1, g1.x, sx1 * g0.x);
    r1.y = fmaf(tx1, g1.y, sx1 * g0.y);
    r1.z = fmaf(tx1, g1.z, sx1 * g0.z);
    r1.w = fmaf(tx1, g1.w, sx1 * g0.w);

    float4* po = out + ((((long)b * D_ + d) * H_ + h) * W_ + w0i) * C4_ + c4;
    po[0]   = r0;
    po[C4_] = r1;
}

extern "C" void kernel_launch(void* const* d_in, const int* in_sizes, int n_in,
                              void* d_out, int out_size)
{
    const float4* in = (const float4*)d_in[0];
    float4* out = (float4*)d_out;
    const int total_threads = B_ * D_ * H_ * (W_ / 2) * C4_;  // 4194304
    const int threads = 256;
    const int blocks = total_threads / threads;                // 16384
    trilerp2_kernel<<<blocks, threads>>>(in, out);
}